// round 8
// baseline (speedup 1.0000x reference)
#include <cuda_runtime.h>

#define NB    2
#define NPTS  8192
#define NDIM  64
#define KSEL  16

// Branch-free insert of (dv, idx) into a register-resident, lexicographically
// ascending (dist, idx) top-16 list. Caller guarantees (dv,idx) < list[15].
__device__ __forceinline__ void ins16(float (&ld)[KSEL], int (&li)[KSEL],
                                      float dv, int idx) {
    int rank = 0;
#pragma unroll
    for (int p = 0; p < KSEL; p++)
        rank += ((ld[p] < dv) || (ld[p] == dv && li[p] < idx)) ? 1 : 0;
#pragma unroll
    for (int p = KSEL - 1; p > 0; p--) {
        bool here  = (p == rank);
        bool shift = (p > rank);
        ld[p] = here ? dv  : (shift ? ld[p - 1] : ld[p]);
        li[p] = here ? idx : (shift ? li[p - 1] : li[p]);
    }
    if (rank == 0) { ld[0] = dv; li[0] = idx; }
}

// ---------------------------------------------------------------------------
// Brute-force KNN: one thread per query point. Logic identical to round 6
// (in-bounds, verified); the ONLY change is the output element type: the
// 4 MB d_out (1,048,576 x 4 B, proven by round-7 OOB) is float32 — indices
// are written as float VALUES (exact: all indices < 2^24).
//   d(n,m) = (sq_n + (-2 * dot(n,m))) + sq_m, fp32, fixed c=0..63 fma order
//   (identical chains for dot and both norms => self-distance == exactly 0).
// Selection: stable (dist, idx)-lexicographic top-16 == top_k tie order.
// Candidate loads are warp-uniform -> L1 broadcast; 4 MB dataset L2-resident.
// ---------------------------------------------------------------------------
__global__ __launch_bounds__(64) void knn_bruteforce(const float* __restrict__ x,
                                                     float* __restrict__ out) {
    int g = blockIdx.x * blockDim.x + threadIdx.x;
    if (g >= NB * NPTS) return;
    int b = g >> 13;              // g / NPTS
    int n = g & (NPTS - 1);       // g % NPTS
    const float* xb = x + b * (NDIM * NPTS);

    // Cache the query point in registers (fully unrolled -> no local memory).
    float q[NDIM];
#pragma unroll
    for (int c = 0; c < NDIM; c++)
        q[c] = xb[c * NPTS + n];

    // Query norm with the same accumulation chain as the candidate norms.
    float sqn = 0.0f;
#pragma unroll
    for (int c = 0; c < NDIM; c++)
        sqn = fmaf(q[c], q[c], sqn);

    float ld[KSEL];
    int   li[KSEL];
#pragma unroll
    for (int p = 0; p < KSEL; p++) {
        ld[p] = __int_as_float(0x7f800000);   // +inf
        li[p] = 0x7fffffff;
    }

    for (int m = 0; m < NPTS; m++) {
        float dot = 0.0f;
        float sqm = 0.0f;
#pragma unroll
        for (int c = 0; c < NDIM; c++) {
            float v = xb[c * NPTS + m];       // warp-uniform load
            dot = fmaf(q[c], v, dot);
            sqm = fmaf(v, v, sqm);
        }
        float d = (sqn + (-2.0f * dot)) + sqm;
        if (d < ld[KSEL - 1] || (d == ld[KSEL - 1] && m < li[KSEL - 1]))
            ins16(ld, li, d, m);
    }

    // Output shape (2, NB, NPTS, KSEL), C-order, float32 values.
    int base0 = (b * NPTS + n) * KSEL;                    // plane 0: nn_idx
    int base1 = NB * NPTS * KSEL + base0;                 // plane 1: center_idx
#pragma unroll
    for (int k = 0; k < KSEL; k++) {
        out[base0 + k] = (float)li[k];
        out[base1 + k] = (float)n;
    }
}

extern "C" void kernel_launch(void* const* d_in, const int* in_sizes, int n_in,
                              void* d_out, int out_size) {
    const float* x = (const float*)d_in[0];
    float* out = (float*)d_out;
    knn_bruteforce<<<(NB * NPTS + 63) / 64, 64>>>(x, out);
}

// round 9
// speedup vs baseline: 1.1021x; 1.1021x over previous
#include <cuda_runtime.h>

#define NB      2
#define NPTS    8192
#define NDIM    64
#define KSEL    16
#define QB      32
#define CB      128
#define THREADS 256

// Precomputed squared norms (allocation-free scratch).
__device__ float g_sq[NB * NPTS];

// lexicographic (distance, index) ascending — matches stable top_k tie order
__device__ __forceinline__ bool keyless(float d1, int i1, float d2, int i2) {
    return (d1 < d2) || (d1 == d2 && i1 < i2);
}

// Branch-free insert into register-resident sorted-16 list.
// Caller guarantees key beats list[15].
__device__ __forceinline__ void ins16(float (&ld)[KSEL], int (&li)[KSEL],
                                      float dv, int idx) {
    int rank = 0;
#pragma unroll
    for (int p = 0; p < KSEL; p++)
        rank += keyless(ld[p], li[p], dv, idx) ? 1 : 0;
#pragma unroll
    for (int p = KSEL - 1; p > 0; p--) {
        bool here  = (p == rank);
        bool shift = (p > rank);
        ld[p] = here ? dv  : (shift ? ld[p - 1] : ld[p]);
        li[p] = here ? idx : (shift ? li[p - 1] : li[p]);
    }
    if (rank == 0) { ld[0] = dv; li[0] = idx; }
}

// ---------------------------------------------------------------------------
// Kernel 1: ||x||^2 per point — SAME sequential fma chain (c=0..63) as the
// dot products below, so self-distance cancels to exactly 0 in fp32.
// ---------------------------------------------------------------------------
__global__ void norms_kernel(const float* __restrict__ x) {
    int p = blockIdx.x * blockDim.x + threadIdx.x;
    if (p >= NB * NPTS) return;
    int b = p >> 13;
    int n = p & (NPTS - 1);
    const float* xb = x + b * (NDIM * NPTS);
    float acc = 0.0f;
#pragma unroll
    for (int c = 0; c < NDIM; c++) {
        float v = xb[c * NPTS + n];            // coalesced across n
        acc = fmaf(v, v, acc);
    }
    g_sq[p] = acc;
}

// ---------------------------------------------------------------------------
// Kernel 2: fused Gram + running top-16 (smem-tiled).
//   grid (NPTS/QB, NB), 256 threads. Block: 32 queries; 64 tiles x 128 cands.
//   Thread (qg = tid>>4, cg = tid&15): queries {2qg, 2qg+1} x candidates
//   {4cg..4cg+3, 64+4cg..+3}. Per-thread register top-16; final 16-way merge
//   per query via shared dump (reuses the 32 KB cs tile exactly).
// ---------------------------------------------------------------------------
__global__ __launch_bounds__(THREADS) void knn_kernel(const float* __restrict__ x,
                                                      float* __restrict__ out) {
    __shared__ __align__(16) float qs[NDIM * QB];   //  8 KB  [k][q]
    __shared__ __align__(16) float cs[NDIM * CB];   // 32 KB  [k][p]; later dump
    __shared__ float cssq[CB];
    __shared__ float qsq[QB];

    const int tid    = threadIdx.x;
    const int b      = blockIdx.y;
    const int n_base = blockIdx.x * QB;
    const float* xb  = x + b * (NDIM * NPTS);
    const float* sqb = g_sq + b * NPTS;

    // Query tile k-major (coalesced) + query norms.
    for (int i = tid; i < NDIM * QB; i += THREADS) {
        int q = i & (QB - 1);
        int k = i >> 5;
        qs[k * QB + q] = xb[k * NPTS + n_base + q];
    }
    if (tid < QB) qsq[tid] = sqb[n_base + tid];
    __syncthreads();

    const int qg = tid >> 4;          // 0..15
    const int cg = tid & 15;          // 0..15
    const float sq0 = qsq[2 * qg];
    const float sq1 = qsq[2 * qg + 1];

    float ld0[KSEL], ld1[KSEL];
    int   li0[KSEL], li1[KSEL];
#pragma unroll
    for (int p = 0; p < KSEL; p++) {
        ld0[p] = __int_as_float(0x7f800000);  li0[p] = 0x7fffffff;
        ld1[p] = __int_as_float(0x7f800000);  li1[p] = 0x7fffffff;
    }

    const float2* qs2 = reinterpret_cast<const float2*>(qs);   // [k*16 + qg]
    const float4* csr = reinterpret_cast<const float4*>(cs);   // [k*32 + ...]
    float4*       csw = reinterpret_cast<float4*>(cs);
    const float4* x4  = reinterpret_cast<const float4*>(xb);

    for (int base = 0; base < NPTS; base += CB) {
        __syncthreads();   // previous tile fully consumed

        // Candidate tile [k][p]: coalesced float4 LDG, conflict-free STS.
        for (int i = tid; i < NDIM * (CB / 4); i += THREADS) {
            int p4 = i & 31;
            int c  = i >> 5;
            csw[c * (CB / 4) + p4] = x4[(c * NPTS + base) / 4 + p4];
        }
        if (tid < CB) cssq[tid] = sqb[base + tid];
        __syncthreads();

        // Gram micro-tile: 2 queries x 8 candidates, sequential k chain.
        float acc0[8], acc1[8];
#pragma unroll
        for (int j = 0; j < 8; j++) { acc0[j] = 0.0f; acc1[j] = 0.0f; }

#pragma unroll 8
        for (int k = 0; k < NDIM; k++) {
            float2 a  = qs2[k * (QB / 2) + qg];          // broadcast
            float4 mA = csr[k * (CB / 4) + cg];          // cands 4cg..4cg+3
            float4 mB = csr[k * (CB / 4) + 16 + cg];     // cands 64+4cg..+3
            acc0[0] = fmaf(a.x, mA.x, acc0[0]);
            acc0[1] = fmaf(a.x, mA.y, acc0[1]);
            acc0[2] = fmaf(a.x, mA.z, acc0[2]);
            acc0[3] = fmaf(a.x, mA.w, acc0[3]);
            acc0[4] = fmaf(a.x, mB.x, acc0[4]);
            acc0[5] = fmaf(a.x, mB.y, acc0[5]);
            acc0[6] = fmaf(a.x, mB.z, acc0[6]);
            acc0[7] = fmaf(a.x, mB.w, acc0[7]);
            acc1[0] = fmaf(a.y, mA.x, acc1[0]);
            acc1[1] = fmaf(a.y, mA.y, acc1[1]);
            acc1[2] = fmaf(a.y, mA.z, acc1[2]);
            acc1[3] = fmaf(a.y, mA.w, acc1[3]);
            acc1[4] = fmaf(a.y, mB.x, acc1[4]);
            acc1[5] = fmaf(a.y, mB.y, acc1[5]);
            acc1[6] = fmaf(a.y, mB.z, acc1[6]);
            acc1[7] = fmaf(a.y, mB.w, acc1[7]);
        }

        // Epilogue + per-thread register selection.
#pragma unroll
        for (int j = 0; j < 8; j++) {
            int c   = (j < 4) ? (4 * cg + j) : (64 + 4 * cg + (j - 4));
            int idx = base + c;
            float sc = cssq[c];
            float d0 = (sq0 + (-2.0f * acc0[j])) + sc;
            float d1 = (sq1 + (-2.0f * acc1[j])) + sc;
            if (keyless(d0, idx, ld0[KSEL - 1], li0[KSEL - 1])) ins16(ld0, li0, d0, idx);
            if (keyless(d1, idx, ld1[KSEL - 1], li1[KSEL - 1])) ins16(ld1, li1, d1, idx);
        }
    }

    // ---- Final merge: reuse cs as dump (4096 floats + 4096 ints = 32 KB). ----
    float* dump_d = cs;
    int*   dump_i = reinterpret_cast<int*>(cs + (NDIM * CB) / 2);

#pragma unroll
    for (int phase = 0; phase < 2; phase++) {
        __syncthreads();
        int slot = (qg * 16 + cg) * KSEL;
#pragma unroll
        for (int e = 0; e < KSEL; e++) {
            dump_d[slot + e] = phase ? ld1[e] : ld0[e];
            dump_i[slot + e] = phase ? li1[e] : li0[e];
        }
        __syncthreads();

        if (tid < 16) {
            const int m = tid;                 // merges query 2m + phase
            float md[KSEL]; int mi[KSEL];
            for (int p = 0; p < KSEL; p++) {
                md[p] = __int_as_float(0x7f800000);
                mi[p] = 0x7fffffff;
            }
            for (int c = 0; c < 16; c++) {
                int s = (m * 16 + c) * KSEL;
                for (int e = 0; e < KSEL; e++) {
                    float d = dump_d[s + e];
                    int   i = dump_i[s + e];
                    if (!keyless(d, i, md[KSEL - 1], mi[KSEL - 1])) break; // sorted
                    int p = KSEL - 1;
                    while (p > 0 && keyless(d, i, md[p - 1], mi[p - 1])) {
                        md[p] = md[p - 1]; mi[p] = mi[p - 1]; p--;
                    }
                    md[p] = d; mi[p] = i;
                }
            }
            int n = n_base + 2 * m + phase;
            int base0 = (b * NPTS + n) * KSEL;           // plane 0: nn_idx
            int base1 = NB * NPTS * KSEL + base0;        // plane 1: center_idx
            for (int k = 0; k < KSEL; k++) {
                out[base0 + k] = (float)mi[k];
                out[base1 + k] = (float)n;
            }
        }
    }
}

extern "C" void kernel_launch(void* const* d_in, const int* in_sizes, int n_in,
                              void* d_out, int out_size) {
    const float* x = (const float*)d_in[0];
    float* out = (float*)d_out;
    norms_kernel<<<(NB * NPTS + THREADS - 1) / THREADS, THREADS>>>(x);
    knn_kernel<<<dim3(NPTS / QB, NB), THREADS>>>(x, out);
}

// round 10
// speedup vs baseline: 1.3748x; 1.2475x over previous
#include <cuda_runtime.h>

#define NB      2
#define NPTS    8192
#define NDIM    64
#define KSEL    16
#define QB      32
#define CB      128
#define THREADS 256

// Precomputed squared norms (allocation-free scratch).
__device__ float g_sq[NB * NPTS];

// lexicographic (distance, index) ascending — stable top_k tie order
__device__ __forceinline__ bool keyless(float d1, int i1, float d2, int i2) {
    return (d1 < d2) || (d1 == d2 && i1 < i2);
}

// Serial insert into a shared sorted-16 list (executed by lane 0 only).
__device__ __forceinline__ void sins16(float* tl_d, int* tl_i, float dv, int idx) {
    if (keyless(dv, idx, tl_d[KSEL - 1], tl_i[KSEL - 1])) {
        int p = KSEL - 1;
        while (p > 0 && keyless(dv, idx, tl_d[p - 1], tl_i[p - 1])) {
            tl_d[p] = tl_d[p - 1];
            tl_i[p] = tl_i[p - 1];
            p--;
        }
        tl_d[p] = dv;
        tl_i[p] = idx;
    }
}

// ---------------------------------------------------------------------------
// Kernel 1: ||x||^2 per point — SAME sequential fma chain (c=0..63) as the
// dot products below, so the self-distance cancels to exactly 0 in fp32.
// ---------------------------------------------------------------------------
__global__ void norms_kernel(const float* __restrict__ x) {
    int p = blockIdx.x * blockDim.x + threadIdx.x;
    if (p >= NB * NPTS) return;
    int b = p >> 13;
    int n = p & (NPTS - 1);
    const float* xb = x + b * (NDIM * NPTS);
    float acc = 0.0f;
#pragma unroll
    for (int c = 0; c < NDIM; c++) {
        float v = xb[c * NPTS + n];
        acc = fmaf(v, v, acc);
    }
    g_sq[p] = acc;
}

// ---------------------------------------------------------------------------
// Kernel 2: fused Gram + warp-cooperative running top-16.
//   grid (NPTS/QB, NB), 256 threads (8 warps). Block: 32 queries; 64 tiles of
//   128 candidates. Thread (qg = tid>>4, cg = tid&15): queries {2qg, 2qg+1} x
//   candidates {4cg..4cg+3, 64+4cg..+3}. ONE sorted top-16 per query in smem,
//   owned by its warp (warp w -> queries 4w..4w+3); candidates screened by
//   threshold + ballot, survivors inserted serially by lane 0.
// ---------------------------------------------------------------------------
__global__ __launch_bounds__(THREADS) void knn_kernel(const float* __restrict__ x,
                                                      float* __restrict__ out) {
    __shared__ __align__(16) float qs[NDIM * QB];   //  8 KB  [k][q]
    __shared__ __align__(16) float cs[NDIM * CB];   // 32 KB  [k][p]
    __shared__ float cssq[CB];
    __shared__ float qsq[QB];
    __shared__ float tld[QB * KSEL];                // 2 KB sorted dists
    __shared__ int   tli[QB * KSEL];                // 2 KB indices

    const int tid    = threadIdx.x;
    const int b      = blockIdx.y;
    const int n_base = blockIdx.x * QB;
    const float* xb  = x + b * (NDIM * NPTS);
    const float* sqb = g_sq + b * NPTS;

    for (int i = tid; i < NDIM * QB; i += THREADS) {
        int q = i & (QB - 1);
        int k = i >> 5;
        qs[k * QB + q] = xb[k * NPTS + n_base + q];
    }
    if (tid < QB) qsq[tid] = sqb[n_base + tid];
    for (int i = tid; i < QB * KSEL; i += THREADS) {
        tld[i] = __int_as_float(0x7f800000);   // +inf
        tli[i] = 0x7fffffff;
    }
    __syncthreads();

    const int lane = tid & 31;
    const int warp = tid >> 5;
    const int qg   = tid >> 4;          // 0..15
    const int cg   = tid & 15;          // 0..15
    const float sq0 = qsq[2 * qg];
    const float sq1 = qsq[2 * qg + 1];

    const float2* qs2 = reinterpret_cast<const float2*>(qs);
    const float4* csr = reinterpret_cast<const float4*>(cs);
    float4*       csw = reinterpret_cast<float4*>(cs);
    const float4* x4  = reinterpret_cast<const float4*>(xb);

    for (int base = 0; base < NPTS; base += CB) {
        __syncthreads();   // previous tile fully consumed

        for (int i = tid; i < NDIM * (CB / 4); i += THREADS) {
            int p4 = i & 31;
            int c  = i >> 5;
            csw[c * (CB / 4) + p4] = x4[(c * NPTS + base) / 4 + p4];
        }
        if (tid < CB) cssq[tid] = sqb[base + tid];
        __syncthreads();

        // --- Gram micro-tile: 2 queries x 8 candidates ---
        float acc0[8], acc1[8];
#pragma unroll
        for (int j = 0; j < 8; j++) { acc0[j] = 0.0f; acc1[j] = 0.0f; }

#pragma unroll 8
        for (int k = 0; k < NDIM; k++) {
            float2 a  = qs2[k * (QB / 2) + qg];          // broadcast
            float4 mA = csr[k * (CB / 4) + cg];          // cands 4cg..4cg+3
            float4 mB = csr[k * (CB / 4) + 16 + cg];     // cands 64+4cg..+3
            acc0[0] = fmaf(a.x, mA.x, acc0[0]);
            acc0[1] = fmaf(a.x, mA.y, acc0[1]);
            acc0[2] = fmaf(a.x, mA.z, acc0[2]);
            acc0[3] = fmaf(a.x, mA.w, acc0[3]);
            acc0[4] = fmaf(a.x, mB.x, acc0[4]);
            acc0[5] = fmaf(a.x, mB.y, acc0[5]);
            acc0[6] = fmaf(a.x, mB.z, acc0[6]);
            acc0[7] = fmaf(a.x, mB.w, acc0[7]);
            acc1[0] = fmaf(a.y, mA.x, acc1[0]);
            acc1[1] = fmaf(a.y, mA.y, acc1[1]);
            acc1[2] = fmaf(a.y, mA.z, acc1[2]);
            acc1[3] = fmaf(a.y, mA.w, acc1[3]);
            acc1[4] = fmaf(a.y, mB.x, acc1[4]);
            acc1[5] = fmaf(a.y, mB.y, acc1[5]);
            acc1[6] = fmaf(a.y, mB.z, acc1[6]);
            acc1[7] = fmaf(a.y, mB.w, acc1[7]);
        }

        // Distance epilogue (registers).
        float d0[8], d1[8];
#pragma unroll
        for (int j = 0; j < 8; j++) {
            int c = (j < 4) ? (4 * cg + j) : (64 + 4 * cg + (j - 4));
            float sc = cssq[c];
            d0[j] = (sq0 + (-2.0f * acc0[j])) + sc;
            d1[j] = (sq1 + (-2.0f * acc1[j])) + sc;
        }

        // --- Warp-cooperative selection. Warp w owns queries 4w..4w+3:
        //   d0: lanes 0-15 -> q 4w,   lanes 16-31 -> q 4w+2
        //   d1: lanes 0-15 -> q 4w+1, lanes 16-31 -> q 4w+3
#pragma unroll
        for (int sub = 0; sub < 2; sub++) {
            const int q_lo = 4 * warp + sub;
            const int q_hi = q_lo + 2;
            const int myq  = q_lo + ((lane >> 4) << 1);
#pragma unroll
            for (int j = 0; j < 8; j++) {
                float d    = (sub == 0) ? d0[j] : d1[j];
                int   cme  = (j < 4) ? (4 * cg + j) : (64 + 4 * cg + (j - 4));
                float thr  = tld[myq * KSEL + KSEL - 1];
                int   thri = tli[myq * KSEL + KSEL - 1];
                bool pass  = keyless(d, base + cme, thr, thri);
                unsigned bal = __ballot_sync(0xffffffffu, pass);
                if (bal) {
                    unsigned lom = bal & 0xffffu;
                    while (lom) {
                        int src = __ffs(lom) - 1;
                        lom &= lom - 1;
                        float dv = __shfl_sync(0xffffffffu, d, src);
                        if (lane == 0) {
                            int c = (j < 4) ? (4 * src + j) : (64 + 4 * src + (j - 4));
                            sins16(tld + q_lo * KSEL, tli + q_lo * KSEL, dv, base + c);
                        }
                    }
                    unsigned him = bal >> 16;
                    while (him) {
                        int s = __ffs(him) - 1;
                        him &= him - 1;
                        float dv = __shfl_sync(0xffffffffu, d, s + 16);
                        if (lane == 0) {
                            int c = (j < 4) ? (4 * s + j) : (64 + 4 * s + (j - 4));
                            sins16(tld + q_hi * KSEL, tli + q_hi * KSEL, dv, base + c);
                        }
                    }
                    __syncwarp();   // lane-0 smem writes visible to whole warp
                }
            }
        }
    }

    // Output (2, NB, NPTS, KSEL), float32 values.
    __syncthreads();
    for (int i = tid; i < QB * KSEL; i += THREADS) {
        int q = i >> 4;
        int k = i & (KSEL - 1);
        int n = n_base + q;
        int base0 = (b * NPTS + n) * KSEL + k;            // plane 0: nn_idx
        int base1 = NB * NPTS * KSEL + base0;             // plane 1: center_idx
        out[base0] = (float)tli[q * KSEL + k];
        out[base1] = (float)n;
    }
}

extern "C" void kernel_launch(void* const* d_in, const int* in_sizes, int n_in,
                              void* d_out, int out_size) {
    const float* x = (const float*)d_in[0];
    float* out = (float*)d_out;
    norms_kernel<<<(NB * NPTS + THREADS - 1) / THREADS, THREADS>>>(x);
    knn_kernel<<<dim3(NPTS / QB, NB), THREADS>>>(x, out);
}